// round 5
// baseline (speedup 1.0000x reference)
#include <cuda_runtime.h>
#include <cuda_bf16.h>
#include <math_constants.h>

// Problem constants
#define Bsz   4
#define Ssz   2048
#define Dsz   1024
#define Hn    16
#define HDim  64
#define Mrows (Bsz * Ssz)   // 8192
#define NELEM (Mrows * Dsz) // 8M
#define WELEM (Dsz * Dsz)   // 1M

// ---------------------------------------------------------------------------
// Scratch (static device globals -- no allocation at runtime)
// ---------------------------------------------------------------------------
__device__ __nv_bfloat16 g_q_h[NELEM], g_q_l[NELEM];
__device__ __nv_bfloat16 g_k_h[NELEM], g_k_l[NELEM];
__device__ __nv_bfloat16 g_v_h[NELEM], g_v_l[NELEM];
__device__ __nv_bfloat16 g_wq_h[WELEM], g_wq_l[WELEM];
__device__ __nv_bfloat16 g_wk_h[WELEM], g_wk_l[WELEM];
__device__ __nv_bfloat16 g_wv_h[WELEM], g_wv_l[WELEM];
__device__ __nv_bfloat16 g_wo_h[WELEM], g_wo_l[WELEM];
__device__ __nv_bfloat16 g_qh_h[NELEM], g_qh_l[NELEM];
__device__ __nv_bfloat16 g_kh_h[NELEM], g_kh_l[NELEM];
__device__ __nv_bfloat16 g_vh_h[NELEM], g_vh_l[NELEM];
__device__ __nv_bfloat16 g_hid_h[NELEM], g_hid_l[NELEM];

// ---------------------------------------------------------------------------
// Helpers
// ---------------------------------------------------------------------------
__device__ __forceinline__ unsigned smem_u32(const void* p) {
    return (unsigned)__cvta_generic_to_shared(p);
}

__device__ __forceinline__ unsigned pack_bf16(float a, float b) {
    __nv_bfloat162 h; h.x = __float2bfloat16(a); h.y = __float2bfloat16(b);
    return *(unsigned*)&h;
}

// fp32x4 -> hi/lo bf16x2 pairs
__device__ __forceinline__ void split4(float4 v, unsigned& h01, unsigned& h23,
                                       unsigned& l01, unsigned& l23) {
    __nv_bfloat16 hx = __float2bfloat16(v.x), hy = __float2bfloat16(v.y);
    __nv_bfloat16 hz = __float2bfloat16(v.z), hw = __float2bfloat16(v.w);
    h01 = pack_bf16(v.x, v.y);
    h23 = pack_bf16(v.z, v.w);
    l01 = pack_bf16(v.x - __bfloat162float(hx), v.y - __bfloat162float(hy));
    l23 = pack_bf16(v.z - __bfloat162float(hz), v.w - __bfloat162float(hw));
}

__device__ __forceinline__ void cp_async16(unsigned saddr, const void* gptr) {
    asm volatile("cp.async.cg.shared.global [%0], [%1], 16;"
                 :: "r"(saddr), "l"(gptr) : "memory");
}
__device__ __forceinline__ void cp_commit() {
    asm volatile("cp.async.commit_group;" ::: "memory");
}
template <int N>
__device__ __forceinline__ void cp_wait() {
    asm volatile("cp.async.wait_group %0;" :: "n"(N) : "memory");
}

__device__ __forceinline__ void ldm_x4(unsigned& r0, unsigned& r1, unsigned& r2, unsigned& r3,
                                       unsigned addr) {
    asm volatile("ldmatrix.sync.aligned.m8n8.x4.shared.b16 {%0,%1,%2,%3}, [%4];"
                 : "=r"(r0), "=r"(r1), "=r"(r2), "=r"(r3) : "r"(addr));
}
__device__ __forceinline__ void ldm_x4_t(unsigned& r0, unsigned& r1, unsigned& r2, unsigned& r3,
                                         unsigned addr) {
    asm volatile("ldmatrix.sync.aligned.m8n8.x4.trans.shared.b16 {%0,%1,%2,%3}, [%4];"
                 : "=r"(r0), "=r"(r1), "=r"(r2), "=r"(r3) : "r"(addr));
}
__device__ __forceinline__ void mma_bf16(float* c, const unsigned* a, unsigned b0, unsigned b1) {
    asm volatile(
        "mma.sync.aligned.m16n8k16.row.col.f32.bf16.bf16.f32 "
        "{%0,%1,%2,%3}, {%4,%5,%6,%7}, {%8,%9}, {%0,%1,%2,%3};"
        : "+f"(c[0]), "+f"(c[1]), "+f"(c[2]), "+f"(c[3])
        : "r"(a[0]), "r"(a[1]), "r"(a[2]), "r"(a[3]), "r"(b0), "r"(b1));
}

// ---------------------------------------------------------------------------
// Split kernel: fp32 -> (hi, lo) bf16, optional scale. 4 elems / thread.
// ---------------------------------------------------------------------------
__global__ __launch_bounds__(256) void split_kernel(
    const float* __restrict__ in, __nv_bfloat16* __restrict__ oh,
    __nv_bfloat16* __restrict__ ol, float s, int n4)
{
    int i = blockIdx.x * blockDim.x + threadIdx.x;
    if (i >= n4) return;
    float4 v = __ldg((const float4*)in + i);
    v.x *= s; v.y *= s; v.z *= s; v.w *= s;
    unsigned h01, h23, l01, l23;
    split4(v, h01, h23, l01, l23);
    unsigned* ohp = (unsigned*)(oh + (size_t)i * 4);
    unsigned* olp = (unsigned*)(ol + (size_t)i * 4);
    ohp[0] = h01; ohp[1] = h23;
    olp[0] = l01; olp[1] = l23;
}

// ---------------------------------------------------------------------------
// bf16 GEMM: C[M,N] = Xh@Wh^T + Xh@Wl^T + Xl@Wh^T (+bias*bscale).
// M=8192, N=K=1024. Block 128x128, K-chunk 32, 3-stage cp.async pipeline.
// 8 warps, warp tile 32x64 (same MMA schedule as round 2).
// Smem per stage: 4 tiles of 128x40 bf16 (80B row stride) = 40960 B.
// ---------------------------------------------------------------------------
#define GTILE_BYTES  (128 * 80)          // 10240
#define GTILE_HALVES (128 * 40)
#define GSTAGE_BYTES (4 * GTILE_BYTES)   // 40960
#define GSTAGES      3
#define GSMEM_TOTAL  (GSTAGES * GSTAGE_BYTES)  // 122880

template <bool SPLIT_OUT>
__global__ __launch_bounds__(256, 1) void gemm_bf16_kernel(
    const __nv_bfloat16* __restrict__ Xh_g, const __nv_bfloat16* __restrict__ Xl_g,
    const __nv_bfloat16* __restrict__ Wh_g, const __nv_bfloat16* __restrict__ Wl_g,
    const float* __restrict__ bias, float bscale,
    float* __restrict__ C, __nv_bfloat16* __restrict__ Ch, __nv_bfloat16* __restrict__ Cl)
{
    extern __shared__ __align__(128) char sm[];
    const unsigned sbase = smem_u32(sm);
    const int tid  = threadIdx.x;
    const int lane = tid & 31;
    const int wid  = tid >> 5;
    const int wm   = wid & 3;
    const int wn   = wid >> 2;
    const int m0   = blockIdx.y * 128;
    const int n0   = blockIdx.x * 128;
    const int lrow = lane & 15;
    const int lcol = (lane >> 4) * 8;

    const int chk = tid & 3;     // 16B chunk within row (4 per row of 64B)
    const int rb  = tid >> 2;    // 0..63

    float acc[2][8][4];
#pragma unroll
    for (int i = 0; i < 2; i++)
#pragma unroll
        for (int j = 0; j < 8; j++)
#pragma unroll
            for (int r = 0; r < 4; r++) acc[i][j][r] = 0.f;

    // issue one stage of cp.async for K-chunk kc into stage s
    auto issue = [&](int kc, int s) {
        unsigned sb = sbase + s * GSTAGE_BYTES;
#pragma unroll
        for (int i = 0; i < 8; i++) {
            const int tile = i >> 1;
            const int r = rb + (i & 1) * 64;
            const __nv_bfloat16* base =
                (tile == 0) ? Xh_g : (tile == 1) ? Xl_g : (tile == 2) ? Wh_g : Wl_g;
            const int row = ((tile < 2) ? m0 : n0) + r;
            const void* gp = base + (size_t)row * 1024 + kc * 32 + chk * 8;
            unsigned sa = sb + tile * GTILE_BYTES + r * 80 + chk * 16;
            cp_async16(sa, gp);
        }
        cp_commit();
    };

    auto compute = [&](int s) {
        const __nv_bfloat16* Ah = (const __nv_bfloat16*)(sm + s * GSTAGE_BYTES);
        const __nv_bfloat16* Al = Ah + GTILE_HALVES;
        const __nv_bfloat16* Bh = Al + GTILE_HALVES;
        const __nv_bfloat16* Bl = Bh + GTILE_HALVES;
#pragma unroll
        for (int ks = 0; ks < 32; ks += 16) {
            unsigned ah[2][4], al[2][4];
#pragma unroll
            for (int mf = 0; mf < 2; mf++) {
                int rA = wm * 32 + mf * 16 + lrow;
                ldm_x4(ah[mf][0], ah[mf][1], ah[mf][2], ah[mf][3],
                       smem_u32(&Ah[rA * 40 + ks + lcol]));
                ldm_x4(al[mf][0], al[mf][1], al[mf][2], al[mf][3],
                       smem_u32(&Al[rA * 40 + ks + lcol]));
            }
#pragma unroll
            for (int nf2 = 0; nf2 < 4; nf2++) {
                int rB = wn * 64 + nf2 * 16 + lrow;
                unsigned bh0, bh1, bh2, bh3, bl0, bl1, bl2, bl3;
                ldm_x4(bh0, bh1, bh2, bh3, smem_u32(&Bh[rB * 40 + ks + lcol]));
                ldm_x4(bl0, bl1, bl2, bl3, smem_u32(&Bl[rB * 40 + ks + lcol]));
#pragma unroll
                for (int mf = 0; mf < 2; mf++) {
                    mma_bf16(acc[mf][nf2 * 2],     ah[mf], bh0, bh2);
                    mma_bf16(acc[mf][nf2 * 2],     ah[mf], bl0, bl2);
                    mma_bf16(acc[mf][nf2 * 2],     al[mf], bh0, bh2);
                    mma_bf16(acc[mf][nf2 * 2 + 1], ah[mf], bh1, bh3);
                    mma_bf16(acc[mf][nf2 * 2 + 1], ah[mf], bl1, bl3);
                    mma_bf16(acc[mf][nf2 * 2 + 1], al[mf], bh1, bh3);
                }
            }
        }
    };

    issue(0, 0);
    issue(1, 1);

    for (int t = 0; t < 32; t++) {
        if (t + 2 < 32) {
            issue(t + 2, (t + 2) % GSTAGES);
            cp_wait<2>();
        } else if (t + 1 < 32) {
            cp_wait<1>();
        } else {
            cp_wait<0>();
        }
        __syncthreads();
        compute(t % GSTAGES);
        __syncthreads();
    }

    // Epilogue
#pragma unroll
    for (int mf = 0; mf < 2; mf++) {
#pragma unroll
        for (int nf = 0; nf < 8; nf++) {
            int row = m0 + wm * 32 + mf * 16 + (lane >> 2);
            int col = n0 + wn * 64 + nf * 8 + (lane & 3) * 2;
            float b0v = bias[col] * bscale, b1v = bias[col + 1] * bscale;
            float x0 = acc[mf][nf][0] + b0v, y0 = acc[mf][nf][1] + b1v;
            float x1 = acc[mf][nf][2] + b0v, y1 = acc[mf][nf][3] + b1v;
            if (SPLIT_OUT) {
                unsigned h0 = pack_bf16(x0, y0);
                unsigned h1 = pack_bf16(x1, y1);
                __nv_bfloat162 t0 = *(__nv_bfloat162*)&h0;
                __nv_bfloat162 t1 = *(__nv_bfloat162*)&h1;
                unsigned l0 = pack_bf16(x0 - __bfloat162float(t0.x), y0 - __bfloat162float(t0.y));
                unsigned l1 = pack_bf16(x1 - __bfloat162float(t1.x), y1 - __bfloat162float(t1.y));
                *(unsigned*)&Ch[(size_t)row * 1024 + col] = h0;
                *(unsigned*)&Cl[(size_t)row * 1024 + col] = l0;
                *(unsigned*)&Ch[(size_t)(row + 8) * 1024 + col] = h1;
                *(unsigned*)&Cl[(size_t)(row + 8) * 1024 + col] = l1;
            } else {
                float2 o0 = {x0, y0};
                float2 o1 = {x1, y1};
                *(float2*)&C[(size_t)row * 1024 + col] = o0;
                *(float2*)&C[(size_t)(row + 8) * 1024 + col] = o1;
            }
        }
    }
}

// ---------------------------------------------------------------------------
// Flash attention, bf16 pre-split inputs, 2-stage cp.async pipeline.
// Block = 64 query rows of one (b,h), 4 warps x 16 rows.
// Stage: Kh|Kl|Vh|Vl, each 64x72 bf16 (144B stride) = 9216 B -> 36864/stage.
// ---------------------------------------------------------------------------
#define ATILE_BYTES  (64 * 144)          // 9216
#define ASTAGE_BYTES (4 * ATILE_BYTES)   // 36864
#define ASMEM_TOTAL  (2 * ASTAGE_BYTES)  // 73728

__global__ __launch_bounds__(128, 1) void attn_bf16_kernel(
    const __nv_bfloat16* __restrict__ qh_h, const __nv_bfloat16* __restrict__ qh_l,
    const __nv_bfloat16* __restrict__ kh_h, const __nv_bfloat16* __restrict__ kh_l,
    const __nv_bfloat16* __restrict__ vh_h, const __nv_bfloat16* __restrict__ vh_l,
    const int* __restrict__ mask,
    __nv_bfloat16* __restrict__ hid_h, __nv_bfloat16* __restrict__ hid_l)
{
    extern __shared__ __align__(128) char sm[];
    const unsigned sbase = smem_u32(sm);
    const int tid  = threadIdx.x;
    const int lane = tid & 31;
    const int wid  = tid >> 5;
    const int bh   = blockIdx.y;
    const int b    = bh >> 4;
    const int h    = bh & 15;
    const int q0   = blockIdx.x * 64;
    const int lrow = lane & 15;
    const int lcol = (lane >> 4) * 8;

    const int chk = tid & 7;    // 16B chunk within 128B row
    const int rb  = tid >> 3;   // 0..15

    // ---- Issue Q (hi,lo) into stage 1's Kh/Kl slots ----
    {
        unsigned sb = sbase + ASTAGE_BYTES;
#pragma unroll
        for (int i = 0; i < 8; i++) {
            const int tile = i >> 2;              // 0 = hi, 1 = lo
            const int r = rb + (i & 3) * 16;
            const __nv_bfloat16* base = (tile == 0) ? qh_h : qh_l;
            const void* gp = base + (size_t)(b * 2048 + q0 + r) * 1024 + h * 64 + chk * 8;
            cp_async16(sb + tile * ATILE_BYTES + r * 144 + chk * 16, gp);
        }
        cp_commit();
    }

    // ---- Issue K/V tile for kt-index t into stage s ----
    auto issueKV = [&](int t, int s) {
        unsigned sb = sbase + s * ASTAGE_BYTES;
        const int kt = t * 64;
#pragma unroll
        for (int i = 0; i < 16; i++) {
            const int tile = i >> 2;              // 0=Kh 1=Kl 2=Vh 3=Vl
            const int r = rb + (i & 3) * 16;
            const __nv_bfloat16* base =
                (tile == 0) ? kh_h : (tile == 1) ? kh_l : (tile == 2) ? vh_h : vh_l;
            const void* gp = base + (size_t)(b * 2048 + kt + r) * 1024 + h * 64 + chk * 8;
            cp_async16(sb + tile * ATILE_BYTES + r * 144 + chk * 16, gp);
        }
        cp_commit();
    };

    issueKV(0, 0);
    cp_wait<0>();
    __syncthreads();

    // ---- Load resident Q fragments from stage 1 ----
    unsigned qfh[4][4], qfl[4][4];
    {
        const __nv_bfloat16* Qh = (const __nv_bfloat16*)(sm + ASTAGE_BYTES);
        const __nv_bfloat16* Ql = Qh + ATILE_BYTES / 2;
#pragma unroll
        for (int ksd = 0; ksd < 4; ksd++) {
            int rQ = wid * 16 + lrow;
            ldm_x4(qfh[ksd][0], qfh[ksd][1], qfh[ksd][2], qfh[ksd][3],
                   smem_u32(&Qh[rQ * 72 + ksd * 16 + lcol]));
            ldm_x4(qfl[ksd][0], qfl[ksd][1], qfl[ksd][2], qfl[ksd][3],
                   smem_u32(&Ql[rQ * 72 + ksd * 16 + lcol]));
        }
    }
    __syncthreads();   // Q consumed; stage 1 free for KV tile 1

    const int row0 = q0 + wid * 16 + (lane >> 2);
    const bool msk0 = (mask[b * 2048 + row0] == 0);
    const bool msk1 = (mask[b * 2048 + row0 + 8] == 0);

    float m_i[2] = {-CUDART_INF_F, -CUDART_INF_F};
    float l_i[2] = {0.f, 0.f};
    float O[8][4];
#pragma unroll
    for (int j = 0; j < 8; j++)
#pragma unroll
        for (int r = 0; r < 4; r++) O[j][r] = 0.f;

    for (int t = 0; t < 32; t++) {
        if (t + 1 < 32) {
            issueKV(t + 1, (t + 1) & 1);
            cp_wait<1>();
        } else {
            cp_wait<0>();
        }
        __syncthreads();

        const __nv_bfloat16* Kh = (const __nv_bfloat16*)(sm + (t & 1) * ASTAGE_BYTES);
        const __nv_bfloat16* Kl = Kh + ATILE_BYTES / 2;
        const __nv_bfloat16* Vh = Kl + ATILE_BYTES / 2;
        const __nv_bfloat16* Vl = Vh + ATILE_BYTES / 2;

        // ---- S = Q @ K^T ----
        float s[8][4];
#pragma unroll
        for (int j = 0; j < 8; j++)
#pragma unroll
            for (int r = 0; r < 4; r++) s[j][r] = 0.f;

#pragma unroll
        for (int ksd = 0; ksd < 4; ksd++) {
#pragma unroll
            for (int nf2 = 0; nf2 < 4; nf2++) {
                int rK = nf2 * 16 + lrow;
                unsigned bh0, bh1, bh2, bh3, bl0, bl1, bl2, bl3;
                ldm_x4(bh0, bh1, bh2, bh3, smem_u32(&Kh[rK * 72 + ksd * 16 + lcol]));
                ldm_x4(bl0, bl1, bl2, bl3, smem_u32(&Kl[rK * 72 + ksd * 16 + lcol]));
                mma_bf16(s[nf2 * 2],     qfh[ksd], bh0, bh2);
                mma_bf16(s[nf2 * 2],     qfh[ksd], bl0, bl2);
                mma_bf16(s[nf2 * 2],     qfl[ksd], bh0, bh2);
                mma_bf16(s[nf2 * 2 + 1], qfh[ksd], bh1, bh3);
                mma_bf16(s[nf2 * 2 + 1], qfh[ksd], bl1, bl3);
                mma_bf16(s[nf2 * 2 + 1], qfl[ksd], bh1, bh3);
            }
        }

        if (msk0) {
#pragma unroll
            for (int j = 0; j < 8; j++) { s[j][0] = -1e9f; s[j][1] = -1e9f; }
        }
        if (msk1) {
#pragma unroll
            for (int j = 0; j < 8; j++) { s[j][2] = -1e9f; s[j][3] = -1e9f; }
        }

        // ---- online softmax ----
        float corr[2];
#pragma unroll
        for (int hf = 0; hf < 2; hf++) {
            float mx = -CUDART_INF_F;
#pragma unroll
            for (int j = 0; j < 8; j++)
                mx = fmaxf(mx, fmaxf(s[j][2 * hf], s[j][2 * hf + 1]));
            mx = fmaxf(mx, __shfl_xor_sync(0xffffffff, mx, 1));
            mx = fmaxf(mx, __shfl_xor_sync(0xffffffff, mx, 2));
            float m_new = fmaxf(m_i[hf], mx);
            corr[hf] = __expf(m_i[hf] - m_new);
            m_i[hf] = m_new;
            float rs = 0.f;
#pragma unroll
            for (int j = 0; j < 8; j++) {
                float p0 = __expf(s[j][2 * hf] - m_new);
                float p1 = __expf(s[j][2 * hf + 1] - m_new);
                s[j][2 * hf] = p0; s[j][2 * hf + 1] = p1;
                rs += p0 + p1;
            }
            rs += __shfl_xor_sync(0xffffffff, rs, 1);
            rs += __shfl_xor_sync(0xffffffff, rs, 2);
            l_i[hf] = l_i[hf] * corr[hf] + rs;
#pragma unroll
            for (int j = 0; j < 8; j++) {
                O[j][2 * hf]     *= corr[hf];
                O[j][2 * hf + 1] *= corr[hf];
            }
        }

        // ---- O += P @ V ----
#pragma unroll
        for (int kg = 0; kg < 4; kg++) {
            int j0 = kg * 2, j1 = kg * 2 + 1;
            unsigned a_hi[4], a_lo[4];
            a_hi[0] = pack_bf16(s[j0][0], s[j0][1]);
            a_hi[1] = pack_bf16(s[j0][2], s[j0][3]);
            a_hi[2] = pack_bf16(s[j1][0], s[j1][1]);
            a_hi[3] = pack_bf16(s[j1][2], s[j1][3]);
            {
                __nv_bfloat162 tt;
                tt = *(__nv_bfloat162*)&a_hi[0];
                a_lo[0] = pack_bf16(s[j0][0] - __bfloat162float(tt.x), s[j0][1] - __bfloat162float(tt.y));
                tt = *(__nv_bfloat162*)&a_hi[1];
                a_lo[1] = pack_bf16(s[j0][2] - __bfloat162float(tt.x), s[j0][3] - __bfloat162float(tt.y));
                tt = *(__nv_bfloat162*)&a_hi[2];
                a_lo[2] = pack_bf16(s[j1][0] - __bfloat162float(tt.x), s[j1][1] - __bfloat162float(tt.y));
                tt = *(__nv_bfloat162*)&a_hi[3];
                a_lo[3] = pack_bf16(s[j1][2] - __bfloat162float(tt.x), s[j1][3] - __bfloat162float(tt.y));
            }
#pragma unroll
            for (int nf2 = 0; nf2 < 4; nf2++) {
                int rV = kg * 16 + lrow;
                unsigned v0, v1, v2, v3, w0, w1, w2, w3;
                ldm_x4_t(v0, v1, v2, v3, smem_u32(&Vh[rV * 72 + nf2 * 16 + lcol]));
                ldm_x4_t(w0, w1, w2, w3, smem_u32(&Vl[rV * 72 + nf2 * 16 + lcol]));
                mma_bf16(O[nf2 * 2],     a_hi, v0, v1);
                mma_bf16(O[nf2 * 2],     a_hi, w0, w1);
                mma_bf16(O[nf2 * 2],     a_lo, v0, v1);
                mma_bf16(O[nf2 * 2 + 1], a_hi, v2, v3);
                mma_bf16(O[nf2 * 2 + 1], a_hi, w2, w3);
                mma_bf16(O[nf2 * 2 + 1], a_lo, v2, v3);
            }
        }
        __syncthreads();
    }

    // ---- Epilogue: normalize + split to hi/lo bf16 ----
    float inv0 = 1.f / l_i[0];
    float inv1 = 1.f / l_i[1];
#pragma unroll
    for (int nf = 0; nf < 8; nf++) {
        int col = h * 64 + nf * 8 + (lane & 3) * 2;
        float x0 = O[nf][0] * inv0, y0 = O[nf][1] * inv0;
        float x1 = O[nf][2] * inv1, y1 = O[nf][3] * inv1;
        unsigned h0 = pack_bf16(x0, y0);
        unsigned h1 = pack_bf16(x1, y1);
        __nv_bfloat162 t0 = *(__nv_bfloat162*)&h0;
        __nv_bfloat162 t1 = *(__nv_bfloat162*)&h1;
        unsigned l0 = pack_bf16(x0 - __bfloat162float(t0.x), y0 - __bfloat162float(t0.y));
        unsigned l1 = pack_bf16(x1 - __bfloat162float(t1.x), y1 - __bfloat162float(t1.y));
        *(unsigned*)&hid_h[(size_t)(b * 2048 + row0) * 1024 + col] = h0;
        *(unsigned*)&hid_l[(size_t)(b * 2048 + row0) * 1024 + col] = l0;
        *(unsigned*)&hid_h[(size_t)(b * 2048 + row0 + 8) * 1024 + col] = h1;
        *(unsigned*)&hid_l[(size_t)(b * 2048 + row0 + 8) * 1024 + col] = l1;
    }
}

// ---------------------------------------------------------------------------
// Launch
// ---------------------------------------------------------------------------
extern "C" void kernel_launch(void* const* d_in, const int* in_sizes, int n_in,
                              void* d_out, int out_size)
{
    const float* q    = (const float*)d_in[0];
    const float* k    = (const float*)d_in[1];
    const float* v    = (const float*)d_in[2];
    const float* Wq   = (const float*)d_in[3];
    const float* bq   = (const float*)d_in[4];
    const float* Wk   = (const float*)d_in[5];
    const float* bk   = (const float*)d_in[6];
    const float* Wv   = (const float*)d_in[7];
    const float* bv   = (const float*)d_in[8];
    const float* Wo   = (const float*)d_in[9];
    const float* bo   = (const float*)d_in[10];
    const int*   mask = (const int*)d_in[11];
    float* out = (float*)d_out;

    // Resolve scratch
    __nv_bfloat16 *q_h, *q_l, *k_h, *k_l, *v_h, *v_l;
    __nv_bfloat16 *wq_h, *wq_l, *wk_h, *wk_l, *wv_h, *wv_l, *wo_h, *wo_l;
    __nv_bfloat16 *qh_h, *qh_l, *kh_h, *kh_l, *vh_h, *vh_l, *hd_h, *hd_l;
    cudaGetSymbolAddress((void**)&q_h, g_q_h);   cudaGetSymbolAddress((void**)&q_l, g_q_l);
    cudaGetSymbolAddress((void**)&k_h, g_k_h);   cudaGetSymbolAddress((void**)&k_l, g_k_l);
    cudaGetSymbolAddress((void**)&v_h, g_v_h);   cudaGetSymbolAddress((void**)&v_l, g_v_l);
    cudaGetSymbolAddress((void**)&wq_h, g_wq_h); cudaGetSymbolAddress((void**)&wq_l, g_wq_l);
    cudaGetSymbolAddress((void**)&wk_h, g_wk_h); cudaGetSymbolAddress((void**)&wk_l, g_wk_l);
    cudaGetSymbolAddress((void**)&wv_h, g_wv_h); cudaGetSymbolAddress((void**)&wv_l, g_wv_l);
    cudaGetSymbolAddress((void**)&wo_h, g_wo_h); cudaGetSymbolAddress((void**)&wo_l, g_wo_l);
    cudaGetSymbolAddress((void**)&qh_h, g_qh_h); cudaGetSymbolAddress((void**)&qh_l, g_qh_l);
    cudaGetSymbolAddress((void**)&kh_h, g_kh_h); cudaGetSymbolAddress((void**)&kh_l, g_kh_l);
    cudaGetSymbolAddress((void**)&vh_h, g_vh_h); cudaGetSymbolAddress((void**)&vh_l, g_vh_l);
    cudaGetSymbolAddress((void**)&hd_h, g_hid_h); cudaGetSymbolAddress((void**)&hd_l, g_hid_l);

    cudaFuncSetAttribute(gemm_bf16_kernel<true>,
                         cudaFuncAttributeMaxDynamicSharedMemorySize, GSMEM_TOTAL);
    cudaFuncSetAttribute(gemm_bf16_kernel<false>,
                         cudaFuncAttributeMaxDynamicSharedMemorySize, GSMEM_TOTAL);
    cudaFuncSetAttribute(attn_bf16_kernel,
                         cudaFuncAttributeMaxDynamicSharedMemorySize, ASMEM_TOTAL);

    const float qscale = 0.125f;   // 1/sqrt(64), folded into Wq/bq

    // Pre-split inputs and weights to bf16 hi/lo
    split_kernel<<<NELEM / 1024, 256>>>(q, q_h, q_l, 1.f, NELEM / 4);
    split_kernel<<<NELEM / 1024, 256>>>(k, k_h, k_l, 1.f, NELEM / 4);
    split_kernel<<<NELEM / 1024, 256>>>(v, v_h, v_l, 1.f, NELEM / 4);
    split_kernel<<<WELEM / 1024, 256>>>(Wq, wq_h, wq_l, qscale, WELEM / 4);
    split_kernel<<<WELEM / 1024, 256>>>(Wk, wk_h, wk_l, 1.f, WELEM / 4);
    split_kernel<<<WELEM / 1024, 256>>>(Wv, wv_h, wv_l, 1.f, WELEM / 4);
    split_kernel<<<WELEM / 1024, 256>>>(Wo, wo_h, wo_l, 1.f, WELEM / 4);

    dim3 ggrid(1024 / 128, Mrows / 128);   // (8, 64)
    gemm_bf16_kernel<true><<<ggrid, 256, GSMEM_TOTAL>>>(
        q_h, q_l, wq_h, wq_l, bq, qscale, nullptr, qh_h, qh_l);
    gemm_bf16_kernel<true><<<ggrid, 256, GSMEM_TOTAL>>>(
        k_h, k_l, wk_h, wk_l, bk, 1.f, nullptr, kh_h, kh_l);
    gemm_bf16_kernel<true><<<ggrid, 256, GSMEM_TOTAL>>>(
        v_h, v_l, wv_h, wv_l, bv, 1.f, nullptr, vh_h, vh_l);

    dim3 agrid(Ssz / 64, Bsz * Hn);        // (32, 64)
    attn_bf16_kernel<<<agrid, 128, ASMEM_TOTAL>>>(
        qh_h, qh_l, kh_h, kh_l, vh_h, vh_l, mask, hd_h, hd_l);

    gemm_bf16_kernel<false><<<ggrid, 256, GSMEM_TOTAL>>>(
        hd_h, hd_l, wo_h, wo_l, bo, 1.f, out, nullptr, nullptr);
}